// round 1
// baseline (speedup 1.0000x reference)
#include <cuda_runtime.h>
#include <cuda_fp16.h>
#include <mma.h>

using namespace nvcuda;

// Problem constants
#define BB     2
#define SQL    2048
#define SKVL   2048
#define DMODEL 1024
#define NH     16
#define HDIM   64
#define MQ     (BB*SQL)    // 4096
#define MKV    (BB*SKVL)   // 4096

// ---------------- scratch (device globals; no runtime allocation) ----------------
__device__ __half g_xq_h [MQ*DMODEL];
__device__ __half g_xkv_h[MKV*DMODEL];
__device__ __half g_wq_h [DMODEL*DMODEL];
__device__ __half g_wk_h [DMODEL*DMODEL];
__device__ __half g_wv_h [DMODEL*DMODEL];
__device__ __half g_wo_h [DMODEL*DMODEL];
__device__ float  g_qf   [MQ*DMODEL];
__device__ float  g_kf   [MKV*DMODEL];
__device__ float  g_vf   [MKV*DMODEL];
__device__ __half g_qh   [MQ*DMODEL];   // [B,H,SQ,HD], pre-scaled by 1/8
__device__ __half g_kh   [MKV*DMODEL];  // [B,H,SKV,HD]
__device__ __half g_vh   [MKV*DMODEL];  // [B,H,SKV,HD]
__device__ __half g_ctx_h[MQ*DMODEL];   // [B,SQ,D]

// ---------------- fp32 -> fp16 convert ----------------
__global__ void cvt_f32_f16(const float* __restrict__ in, __half* __restrict__ out, int n4) {
    int i = blockIdx.x * blockDim.x + threadIdx.x;
    if (i >= n4) return;
    float4 v = reinterpret_cast<const float4*>(in)[i];
    __half2 a = __floats2half2_rn(v.x, v.y);
    __half2 b = __floats2half2_rn(v.z, v.w);
    reinterpret_cast<__half2*>(out)[2*i]   = a;
    reinterpret_cast<__half2*>(out)[2*i+1] = b;
}

// ---------------- WMMA NT GEMM: C[M,N] = A[M,K] * B[N,K]^T (half in, f32 out) ----------------
#define GBM 128
#define GBN 128
#define GBK 32
#define GLD 40   // padded lda for smem (half, mult of 8)

__global__ __launch_bounds__(256)
void gemm_nt(const __half* __restrict__ A, const __half* __restrict__ B,
             float* __restrict__ C, int M, int N, int K) {
    __shared__ __half As[GBM * GLD];
    __shared__ __half Bs[GBN * GLD];

    int tid  = threadIdx.x;
    int warp = tid >> 5;
    int wm   = warp & 3;   // 0..3  -> 32 rows each
    int wn   = warp >> 2;  // 0..1  -> 64 cols each
    int bm   = blockIdx.y * GBM;
    int bn   = blockIdx.x * GBN;

    wmma::fragment<wmma::accumulator, 16, 16, 16, float> acc[2][4];
    #pragma unroll
    for (int i = 0; i < 2; i++)
        #pragma unroll
        for (int j = 0; j < 4; j++)
            wmma::fill_fragment(acc[i][j], 0.0f);

    int lrow = tid >> 2;          // 0..63
    int lcol = (tid & 3) * 8;     // 0,8,16,24

    for (int k0 = 0; k0 < K; k0 += GBK) {
        #pragma unroll
        for (int p = 0; p < 2; p++) {
            int r = lrow + p * 64;
            *reinterpret_cast<float4*>(As + r * GLD + lcol) =
                *reinterpret_cast<const float4*>(A + (size_t)(bm + r) * K + k0 + lcol);
            *reinterpret_cast<float4*>(Bs + r * GLD + lcol) =
                *reinterpret_cast<const float4*>(B + (size_t)(bn + r) * K + k0 + lcol);
        }
        __syncthreads();

        #pragma unroll
        for (int kk = 0; kk < GBK; kk += 16) {
            wmma::fragment<wmma::matrix_a, 16, 16, 16, __half, wmma::row_major> af[2];
            wmma::fragment<wmma::matrix_b, 16, 16, 16, __half, wmma::col_major> bf[4];
            #pragma unroll
            for (int i = 0; i < 2; i++)
                wmma::load_matrix_sync(af[i], As + (wm * 32 + i * 16) * GLD + kk, GLD);
            #pragma unroll
            for (int j = 0; j < 4; j++)
                wmma::load_matrix_sync(bf[j], Bs + (wn * 64 + j * 16) * GLD + kk, GLD);
            #pragma unroll
            for (int i = 0; i < 2; i++)
                #pragma unroll
                for (int j = 0; j < 4; j++)
                    wmma::mma_sync(acc[i][j], af[i], bf[j], acc[i][j]);
        }
        __syncthreads();
    }

    #pragma unroll
    for (int i = 0; i < 2; i++)
        #pragma unroll
        for (int j = 0; j < 4; j++)
            wmma::store_matrix_sync(
                C + (size_t)(bm + wm * 32 + i * 16) * N + bn + wn * 64 + j * 16,
                acc[i][j], N, wmma::mem_row_major);
}

// ---------------- bias + interleaved RoPE + relayout to [B,H,S,HD] fp16 ----------------
__global__ void rope_perm(const float* __restrict__ C, const float* __restrict__ bias,
                          __half* __restrict__ out, int S, float scale) {
    int idx = blockIdx.x * blockDim.x + threadIdx.x;
    int total = BB * S * NH * (HDIM / 2);
    if (idx >= total) return;
    int pair = idx & 31;
    int h    = (idx >> 5) & (NH - 1);
    int s    = (idx >> 9) & (S - 1);       // S == 2048
    int b    = idx >> 20;

    int din = h * HDIM + pair * 2;
    const float* src = C + (size_t)(b * S + s) * DMODEL + din;
    float e = src[0] + bias[din];
    float o = src[1] + bias[din + 1];

    float freq = expf(-(float)pair * (9.210340371976184f / 32.0f)); // ln(10000)/32
    float ang  = (float)s * freq;
    float cs   = cosf(ang);
    float sn   = sinf(ang);
    float re = (e * cs - o * sn) * scale;
    float ro = (e * sn + o * cs) * scale;

    __half* dst = out + ((size_t)(b * NH + h) * S + s) * HDIM + pair * 2;
    dst[0] = __float2half(re);
    dst[1] = __float2half(ro);
}

// ---------------- bias + relayout V to [B,H,S,HD] fp16 ----------------
__global__ void v_perm(const float* __restrict__ C, const float* __restrict__ bias,
                       __half* __restrict__ out, int S) {
    int idx = blockIdx.x * blockDim.x + threadIdx.x;
    int total = BB * S * DMODEL;
    if (idx >= total) return;
    int d = idx & (DMODEL - 1);
    int s = (idx >> 10) & (S - 1);
    int b = idx >> 21;
    int h = d >> 6;
    int c = d & 63;
    out[((size_t)(b * NH + h) * S + s) * HDIM + c] = __float2half(C[idx] + bias[d]);
}

// ---------------- flash attention: 64-query tiles, 64-key tiles, WMMA ----------------
#define FT    64
#define FLD   72   // padded leading dim (works for half & float frags)

extern __shared__ char fsmem[];

__global__ __launch_bounds__(256)
void flash_kernel(const __half* __restrict__ Q, const __half* __restrict__ K,
                  const __half* __restrict__ V, __half* __restrict__ CTX) {
    __half* Qs = reinterpret_cast<__half*>(fsmem);           // 64*72
    __half* Ks = Qs + 64 * FLD;
    __half* Vs = Ks + 64 * FLD;
    __half* Ps = Vs + 64 * FLD;
    float*  Sf = reinterpret_cast<float*>(Ps + 64 * FLD);    // 64*72 f32
    float*  OT = Sf + 64 * FLD;
    float*  mrow = OT + 64 * FLD;
    float*  lrow = mrow + 64;
    float*  arow = lrow + 64;

    int tid  = threadIdx.x;
    int warp = tid >> 5;
    int b    = blockIdx.z;
    int h    = blockIdx.y;
    int q0   = blockIdx.x * FT;

    const __half* qptr  = Q + ((size_t)(b * NH + h) * SQL + q0) * HDIM;
    const __half* kbase = K + (size_t)(b * NH + h) * SKVL * HDIM;
    const __half* vbase = V + (size_t)(b * NH + h) * SKVL * HDIM;

    // load Q tile
    for (int i = tid; i < 64 * 8; i += 256) {
        int r = i >> 3, c = (i & 7) * 8;
        *reinterpret_cast<float4*>(Qs + r * FLD + c) =
            *reinterpret_cast<const float4*>(qptr + r * HDIM + c);
    }
    if (tid < 64) { mrow[tid] = -1e30f; lrow[tid] = 0.0f; }

    float Oreg[16];
    #pragma unroll
    for (int i = 0; i < 16; i++) Oreg[i] = 0.0f;
    int orow = tid >> 2;
    int ocol = (tid & 3) * 16;
    int t0   = warp * 2;

    for (int kt = 0; kt < SKVL; kt += FT) {
        for (int i = tid; i < 64 * 8; i += 256) {
            int r = i >> 3, c = (i & 7) * 8;
            *reinterpret_cast<float4*>(Ks + r * FLD + c) =
                *reinterpret_cast<const float4*>(kbase + (size_t)(kt + r) * HDIM + c);
            *reinterpret_cast<float4*>(Vs + r * FLD + c) =
                *reinterpret_cast<const float4*>(vbase + (size_t)(kt + r) * HDIM + c);
        }
        __syncthreads();

        // S = Q K^T (Q pre-scaled by 1/sqrt(HD))
        #pragma unroll
        for (int t = 0; t < 2; t++) {
            int ti = (t0 + t) >> 2, tj = (t0 + t) & 3;
            wmma::fragment<wmma::accumulator, 16, 16, 16, float> s_acc;
            wmma::fill_fragment(s_acc, 0.0f);
            #pragma unroll
            for (int kk = 0; kk < 64; kk += 16) {
                wmma::fragment<wmma::matrix_a, 16, 16, 16, __half, wmma::row_major> af;
                wmma::fragment<wmma::matrix_b, 16, 16, 16, __half, wmma::col_major> bf;
                wmma::load_matrix_sync(af, Qs + (ti * 16) * FLD + kk, FLD);
                wmma::load_matrix_sync(bf, Ks + (tj * 16) * FLD + kk, FLD);
                wmma::mma_sync(s_acc, af, bf, s_acc);
            }
            wmma::store_matrix_sync(Sf + (ti * 16) * FLD + tj * 16, s_acc, FLD, wmma::mem_row_major);
        }
        __syncthreads();

        // online softmax: 4 lanes per row
        {
            int row = tid >> 2, qq = tid & 3;
            float* srow = Sf + row * FLD + qq * 16;
            float mx = -1e30f;
            #pragma unroll
            for (int i = 0; i < 16; i++) mx = fmaxf(mx, srow[i]);
            mx = fmaxf(mx, __shfl_xor_sync(0xffffffffu, mx, 1));
            mx = fmaxf(mx, __shfl_xor_sync(0xffffffffu, mx, 2));
            float m_old = mrow[row];
            float m_new = fmaxf(m_old, mx);
            float sum = 0.0f;
            __half* prow = Ps + row * FLD + qq * 16;
            #pragma unroll
            for (int i = 0; i < 16; i++) {
                float p = __expf(srow[i] - m_new);
                prow[i] = __float2half(p);
                sum += p;
            }
            sum += __shfl_xor_sync(0xffffffffu, sum, 1);
            sum += __shfl_xor_sync(0xffffffffu, sum, 2);
            if (qq == 0) {
                float alpha = __expf(m_old - m_new);
                arow[row] = alpha;
                lrow[row] = lrow[row] * alpha + sum;
                mrow[row] = m_new;
            }
        }
        __syncthreads();

        // O_tile = P @ V
        #pragma unroll
        for (int t = 0; t < 2; t++) {
            int ti = (t0 + t) >> 2, tj = (t0 + t) & 3;
            wmma::fragment<wmma::accumulator, 16, 16, 16, float> o_acc;
            wmma::fill_fragment(o_acc, 0.0f);
            #pragma unroll
            for (int kk = 0; kk < 64; kk += 16) {
                wmma::fragment<wmma::matrix_a, 16, 16, 16, __half, wmma::row_major> af;
                wmma::fragment<wmma::matrix_b, 16, 16, 16, __half, wmma::row_major> bf;
                wmma::load_matrix_sync(af, Ps + (ti * 16) * FLD + kk, FLD);
                wmma::load_matrix_sync(bf, Vs + kk * FLD + tj * 16, FLD);
                wmma::mma_sync(o_acc, af, bf, o_acc);
            }
            wmma::store_matrix_sync(OT + (ti * 16) * FLD + tj * 16, o_acc, FLD, wmma::mem_row_major);
        }
        __syncthreads();

        // rescale + accumulate into registers
        {
            float alpha = arow[orow];
            float* otp = OT + orow * FLD + ocol;
            #pragma unroll
            for (int i = 0; i < 16; i++) Oreg[i] = Oreg[i] * alpha + otp[i];
        }
        __syncthreads();
    }

    float invl = 1.0f / lrow[orow];
    __half* optr = CTX + ((size_t)(b * SQL) + q0 + orow) * DMODEL + h * HDIM + ocol;
    #pragma unroll
    for (int i = 0; i < 16; i++) optr[i] = __float2half(Oreg[i] * invl);
}

// ---------------- output bias ----------------
__global__ void bias_add(float* __restrict__ out, const float* __restrict__ bias, int n) {
    int i = blockIdx.x * blockDim.x + threadIdx.x;
    if (i < n) out[i] += bias[i & (DMODEL - 1)];
}

// ---------------- host ----------------
#define FSMEM_BYTES (4 * 64 * FLD * 2 + 2 * 64 * FLD * 4 + 3 * 64 * 4)

extern "C" void kernel_launch(void* const* d_in, const int* in_sizes, int n_in,
                              void* d_out, int out_size) {
    const float* x_q  = (const float*)d_in[0];
    const float* x_kv = (const float*)d_in[1];
    const float* wq   = (const float*)d_in[2];
    const float* bq   = (const float*)d_in[3];
    const float* wk   = (const float*)d_in[4];
    const float* bk   = (const float*)d_in[5];
    const float* wv   = (const float*)d_in[6];
    const float* bv   = (const float*)d_in[7];
    const float* wo   = (const float*)d_in[8];
    const float* bo   = (const float*)d_in[9];
    float* out = (float*)d_out;

    void *p_xq, *p_xkv, *p_wq, *p_wk, *p_wv, *p_wo;
    void *p_qf, *p_kf, *p_vf, *p_qh, *p_kh, *p_vh, *p_ctx;
    cudaGetSymbolAddress(&p_xq,  g_xq_h);
    cudaGetSymbolAddress(&p_xkv, g_xkv_h);
    cudaGetSymbolAddress(&p_wq,  g_wq_h);
    cudaGetSymbolAddress(&p_wk,  g_wk_h);
    cudaGetSymbolAddress(&p_wv,  g_wv_h);
    cudaGetSymbolAddress(&p_wo,  g_wo_h);
    cudaGetSymbolAddress(&p_qf,  g_qf);
    cudaGetSymbolAddress(&p_kf,  g_kf);
    cudaGetSymbolAddress(&p_vf,  g_vf);
    cudaGetSymbolAddress(&p_qh,  g_qh);
    cudaGetSymbolAddress(&p_kh,  g_kh);
    cudaGetSymbolAddress(&p_vh,  g_vh);
    cudaGetSymbolAddress(&p_ctx, g_ctx_h);

    cudaFuncSetAttribute(flash_kernel, cudaFuncAttributeMaxDynamicSharedMemorySize, FSMEM_BYTES);

    const int CT = 256;
    // converts (n always multiple of 4)
    int nX = MQ * DMODEL / 4;
    int nW = DMODEL * DMODEL / 4;
    cvt_f32_f16<<<(nX + CT - 1) / CT, CT>>>(x_q,  (__half*)p_xq,  nX);
    cvt_f32_f16<<<(nX + CT - 1) / CT, CT>>>(x_kv, (__half*)p_xkv, nX);
    cvt_f32_f16<<<(nW + CT - 1) / CT, CT>>>(wq, (__half*)p_wq, nW);
    cvt_f32_f16<<<(nW + CT - 1) / CT, CT>>>(wk, (__half*)p_wk, nW);
    cvt_f32_f16<<<(nW + CT - 1) / CT, CT>>>(wv, (__half*)p_wv, nW);
    cvt_f32_f16<<<(nW + CT - 1) / CT, CT>>>(wo, (__half*)p_wo, nW);

    // projections
    dim3 ggrid(DMODEL / GBN, MQ / GBM);
    gemm_nt<<<ggrid, 256>>>((const __half*)p_xq,  (const __half*)p_wq, (float*)p_qf, MQ,  DMODEL, DMODEL);
    gemm_nt<<<ggrid, 256>>>((const __half*)p_xkv, (const __half*)p_wk, (float*)p_kf, MKV, DMODEL, DMODEL);
    gemm_nt<<<ggrid, 256>>>((const __half*)p_xkv, (const __half*)p_wv, (float*)p_vf, MKV, DMODEL, DMODEL);

    // bias + rope + relayout
    int nR = BB * SQL * NH * (HDIM / 2);
    rope_perm<<<(nR + CT - 1) / CT, CT>>>((const float*)p_qf, bq, (__half*)p_qh, SQL, 0.125f);
    rope_perm<<<(nR + CT - 1) / CT, CT>>>((const float*)p_kf, bk, (__half*)p_kh, SKVL, 1.0f);
    int nV = BB * SKVL * DMODEL;
    v_perm<<<(nV + CT - 1) / CT, CT>>>((const float*)p_vf, bv, (__half*)p_vh, SKVL);

    // flash attention
    dim3 fgrid(SQL / FT, NH, BB);
    flash_kernel<<<fgrid, 256, FSMEM_BYTES>>>((const __half*)p_qh, (const __half*)p_kh,
                                              (const __half*)p_vh, (__half*)p_ctx);

    // output projection + bias
    gemm_nt<<<ggrid, 256>>>((const __half*)p_ctx, (const __half*)p_wo, out, MQ, DMODEL, DMODEL);
    int nO = MQ * DMODEL;
    bias_add<<<(nO + CT - 1) / CT, CT>>>(out, bo, nO);
}

// round 2
// speedup vs baseline: 1.7302x; 1.7302x over previous
#include <cuda_runtime.h>
#include <cuda_fp16.h>
#include <mma.h>
#include <stdint.h>

using namespace nvcuda;

// Problem constants
#define BB     2
#define SQL    2048
#define SKVL   2048
#define DMODEL 1024
#define NH     16
#define HDIM   64
#define MQ     (BB*SQL)    // 4096
#define MKV    (BB*SKVL)   // 4096

// ---------------- scratch (device globals; no runtime allocation) ----------------
__device__ __half g_xq_h [MQ*DMODEL];
__device__ __half g_xkv_h[MKV*DMODEL];
__device__ __half g_wq_h [DMODEL*DMODEL];
__device__ __half g_wk_h [DMODEL*DMODEL];
__device__ __half g_wv_h [DMODEL*DMODEL];
__device__ __half g_wo_h [DMODEL*DMODEL];
__device__ __half g_qh   [MQ*DMODEL];   // [B,H,SQ,HD], pre-scaled by 1/8, rope applied
__device__ __half g_kh   [MKV*DMODEL];  // [B,H,SKV,HD], rope applied
__device__ __half g_vh   [MKV*DMODEL];  // [B,H,SKV,HD]
__device__ __half g_ctx_h[MQ*DMODEL];   // [B,SQ,D]

// ---------------- cp.async helpers ----------------
__device__ __forceinline__ void cp16(void* smem, const void* gmem) {
    uint32_t s = (uint32_t)__cvta_generic_to_shared(smem);
    asm volatile("cp.async.cg.shared.global [%0], [%1], 16;\n" :: "r"(s), "l"(gmem));
}
__device__ __forceinline__ void cp_commit() { asm volatile("cp.async.commit_group;\n"); }
template<int N> __device__ __forceinline__ void cp_wait() {
    asm volatile("cp.async.wait_group %0;\n" :: "n"(N));
}

// ---------------- fp32 -> fp16 convert ----------------
__global__ void cvt_f32_f16(const float* __restrict__ in, __half* __restrict__ out, int n4) {
    int i = blockIdx.x * blockDim.x + threadIdx.x;
    if (i >= n4) return;
    float4 v = reinterpret_cast<const float4*>(in)[i];
    __half2 a = __floats2half2_rn(v.x, v.y);
    __half2 b = __floats2half2_rn(v.z, v.w);
    reinterpret_cast<__half2*>(out)[2*i]   = a;
    reinterpret_cast<__half2*>(out)[2*i+1] = b;
}

// ---------------- fused WMMA NT GEMM, double-buffered cp.async ----------------
// C[M,N] = A[M,K] * B[N,K]^T, M=4096, N=K=1024.
// MODE 0: f32 out = acc + bias   (final output projection)
// MODE 1: interleaved RoPE + bias + scale, half out to [B,H,S,HD]   (Q / K)
// MODE 2: bias, half out to [B,H,S,HD]                              (V)
#define GBM 128
#define GBN 128
#define GBK 32
#define GLD 40   // padded lda for smem (half, mult of 8)

// acc fragment layout (sm_80+ de-facto, m16n16k16 f32):
//   elem e: row = (lane>>2) + 8*((e>>1)&1), col = (lane&3)*2 + (e&1) + 8*(e>>2)

template<int MODE>
__global__ __launch_bounds__(256)
void gemm_fused(const __half* __restrict__ A, const __half* __restrict__ Bm,
                const float* __restrict__ bias, void* __restrict__ Cout, float scale) {
    __shared__ __half As[2][GBM * GLD];
    __shared__ __half Bs[2][GBN * GLD];

    const int K = 1024, N = 1024;
    int tid  = threadIdx.x;
    int lane = tid & 31;
    int warp = tid >> 5;
    int wm   = warp & 3;
    int wn   = warp >> 2;
    int bm   = blockIdx.y * GBM;
    int bn   = blockIdx.x * GBN;

    wmma::fragment<wmma::accumulator, 16, 16, 16, float> acc[2][4];
    #pragma unroll
    for (int i = 0; i < 2; i++)
        #pragma unroll
        for (int j = 0; j < 4; j++)
            wmma::fill_fragment(acc[i][j], 0.0f);

    // stage loader: 512 chunks of 16B per matrix, 2 per thread
    auto load_stage = [&](int st, int k0) {
        #pragma unroll
        for (int p = 0; p < 2; p++) {
            int i = tid + p * 256;
            int r = i >> 2, c = (i & 3) * 8;
            cp16(&As[st][r * GLD + c], A  + (size_t)(bm + r) * K + k0 + c);
            cp16(&Bs[st][r * GLD + c], Bm + (size_t)(bn + r) * K + k0 + c);
        }
    };

    load_stage(0, 0);
    cp_commit();

    const int NK = K / GBK; // 32
    for (int kt = 0; kt < NK; kt++) {
        int st = kt & 1;
        if (kt + 1 < NK) { load_stage(st ^ 1, (kt + 1) * GBK); cp_commit(); cp_wait<1>(); }
        else             { cp_wait<0>(); }
        __syncthreads();

        #pragma unroll
        for (int kk = 0; kk < GBK; kk += 16) {
            wmma::fragment<wmma::matrix_a, 16, 16, 16, __half, wmma::row_major> af[2];
            wmma::fragment<wmma::matrix_b, 16, 16, 16, __half, wmma::col_major> bf[4];
            #pragma unroll
            for (int i = 0; i < 2; i++)
                wmma::load_matrix_sync(af[i], &As[st][(wm * 32 + i * 16) * GLD + kk], GLD);
            #pragma unroll
            for (int j = 0; j < 4; j++)
                wmma::load_matrix_sync(bf[j], &Bs[st][(wn * 64 + j * 16) * GLD + kk], GLD);
            #pragma unroll
            for (int i = 0; i < 2; i++)
                #pragma unroll
                for (int j = 0; j < 4; j++)
                    wmma::mma_sync(acc[i][j], af[i], bf[j], acc[i][j]);
        }
        __syncthreads();
    }

    // ---- fused epilogue ----
    #pragma unroll
    for (int i = 0; i < 2; i++) {
        #pragma unroll
        for (int j = 0; j < 4; j++) {
            int r0 = bm + wm * 32 + i * 16 + (lane >> 2);
            int c0 = bn + wn * 64 + j * 16 + (lane & 3) * 2;
            const float* x = acc[i][j].x;

            if (MODE == 0) {
                float* C = (float*)Cout;
                float2 v;
                v.x = x[0] + bias[c0];     v.y = x[1] + bias[c0 + 1];
                *(float2*)(C + (size_t)r0 * N + c0) = v;
                v.x = x[2] + bias[c0];     v.y = x[3] + bias[c0 + 1];
                *(float2*)(C + (size_t)(r0 + 8) * N + c0) = v;
                v.x = x[4] + bias[c0 + 8]; v.y = x[5] + bias[c0 + 9];
                *(float2*)(C + (size_t)r0 * N + c0 + 8) = v;
                v.x = x[6] + bias[c0 + 8]; v.y = x[7] + bias[c0 + 9];
                *(float2*)(C + (size_t)(r0 + 8) * N + c0 + 8) = v;
            } else {
                __half* Oh = (__half*)Cout;
                #pragma unroll
                for (int p = 0; p < 4; p++) {
                    int row = r0 + ((p & 1) ? 8 : 0);       // p: 0->(0,1) 1->(2,3) 2->(4,5) 3->(6,7)
                    int col = c0 + ((p & 2) ? 8 : 0);
                    float xe = x[p * 2]     + bias[col];
                    float xo = x[p * 2 + 1] + bias[col + 1];
                    int head = col >> 6;
                    int hd   = col & 63;
                    int s    = row & (SQL - 1);
                    int bi   = row >> 11;
                    float re, ro;
                    if (MODE == 1) {
                        int pr = hd >> 1;
                        float freq = expf(-(float)pr * (9.210340371976184f / 32.0f));
                        float ang  = (float)s * freq;
                        float cs = cosf(ang), sn = sinf(ang);
                        re = (xe * cs - xo * sn) * scale;
                        ro = (xe * sn + xo * cs) * scale;
                    } else {
                        re = xe; ro = xo;
                    }
                    __half2 hv = __floats2half2_rn(re, ro);
                    *(__half2*)(Oh + ((size_t)(bi * NH + head) * SQL + s) * HDIM + hd) = hv;
                }
            }
        }
    }
}

// ---------------- flash attention v2: 128-query tiles, register softmax ----------------
#define FQT  128
#define FKT  64
#define FLD  72
#define KVS  (FKT * FLD)   // one K or V stage, in halfs

#define FSMEM_BYTES ((FQT*FLD + 2*KVS + 2*KVS + FQT*FLD) * 2)

extern __shared__ __half fsh[];

__global__ __launch_bounds__(256)
void flash2(const __half* __restrict__ Q, const __half* __restrict__ K,
            const __half* __restrict__ V, __half* __restrict__ CTX) {
    __half* Qs = fsh;                 // FQT x FLD
    __half* Ks = Qs + FQT * FLD;      // 2 stages x FKT x FLD
    __half* Vs = Ks + 2 * KVS;        // 2 stages
    __half* Ps = Vs + 2 * KVS;        // FQT x FLD (per-warp private 16-row slices)

    int tid  = threadIdx.x;
    int lane = tid & 31;
    int warp = tid >> 5;
    int b    = blockIdx.z;
    int h    = blockIdx.y;
    int q0   = blockIdx.x * FQT;

    const __half* qptr  = Q + ((size_t)(b * NH + h) * SQL + q0) * HDIM;
    const __half* kbase = K + (size_t)(b * NH + h) * SKVL * HDIM;
    const __half* vbase = V + (size_t)(b * NH + h) * SKVL * HDIM;

    // load Q tile (128 x 64): 1024 x 16B chunks
    for (int i = tid; i < FQT * 8; i += 256) {
        int r = i >> 3, c = (i & 7) * 8;
        *(float4*)(Qs + r * FLD + c) = *(const float4*)(qptr + r * HDIM + c);
    }

    // KV stage loader: K 512 chunks + V 512 chunks
    auto copy_kv = [&](int st, int kt) {
        #pragma unroll
        for (int p = 0; p < 4; p++) {
            int i = tid + p * 256;
            int r = (i >> 3) & 63, c = (i & 7) * 8;
            if (i < 512)
                cp16(Ks + st * KVS + r * FLD + c, kbase + (size_t)(kt + r) * HDIM + c);
            else
                cp16(Vs + st * KVS + r * FLD + c, vbase + (size_t)(kt + r) * HDIM + c);
        }
    };

    copy_kv(0, 0);
    cp_commit();

    // per-thread softmax state (rows lane>>2 and lane>>2+8 of this warp's 16-row slice)
    float m0 = -1e30f, m1 = -1e30f, l0 = 0.0f, l1 = 0.0f;

    wmma::fragment<wmma::accumulator, 16, 16, 16, float> O[4];
    #pragma unroll
    for (int j = 0; j < 4; j++) wmma::fill_fragment(O[j], 0.0f);

    int wrow = warp * 16;           // this warp's Q-row base within tile
    int cb   = (lane & 3) * 2;      // fragment col base

    const int NT = SKVL / FKT;  // 32
    for (int t = 0; t < NT; t++) {
        int st = t & 1;
        if (t + 1 < NT) { copy_kv(st ^ 1, (t + 1) * FKT); cp_commit(); cp_wait<1>(); }
        else            { cp_wait<0>(); }
        __syncthreads();

        // ---- S = Q K^T (Q pre-scaled) ----
        wmma::fragment<wmma::accumulator, 16, 16, 16, float> S[4];
        #pragma unroll
        for (int j = 0; j < 4; j++) wmma::fill_fragment(S[j], 0.0f);
        #pragma unroll
        for (int kk = 0; kk < HDIM; kk += 16) {
            wmma::fragment<wmma::matrix_a, 16, 16, 16, __half, wmma::row_major> af;
            wmma::load_matrix_sync(af, Qs + wrow * FLD + kk, FLD);
            #pragma unroll
            for (int j = 0; j < 4; j++) {
                wmma::fragment<wmma::matrix_b, 16, 16, 16, __half, wmma::col_major> bf;
                wmma::load_matrix_sync(bf, Ks + st * KVS + (j * 16) * FLD + kk, FLD);
                wmma::mma_sync(S[j], af, bf, S[j]);
            }
        }

        // ---- online softmax in registers ----
        float mx0 = -1e30f, mx1 = -1e30f;
        #pragma unroll
        for (int j = 0; j < 4; j++) {
            const float* x = S[j].x;
            mx0 = fmaxf(mx0, fmaxf(fmaxf(x[0], x[1]), fmaxf(x[4], x[5])));
            mx1 = fmaxf(mx1, fmaxf(fmaxf(x[2], x[3]), fmaxf(x[6], x[7])));
        }
        mx0 = fmaxf(mx0, __shfl_xor_sync(0xffffffffu, mx0, 1));
        mx0 = fmaxf(mx0, __shfl_xor_sync(0xffffffffu, mx0, 2));
        mx1 = fmaxf(mx1, __shfl_xor_sync(0xffffffffu, mx1, 1));
        mx1 = fmaxf(mx1, __shfl_xor_sync(0xffffffffu, mx1, 2));

        float mn0 = fmaxf(m0, mx0), mn1 = fmaxf(m1, mx1);
        float a0  = __expf(m0 - mn0), a1 = __expf(m1 - mn1);

        __half* prow0 = Ps + (wrow + (lane >> 2)) * FLD;
        __half* prow1 = prow0 + 8 * FLD;
        float s0 = 0.0f, s1 = 0.0f;
        #pragma unroll
        for (int j = 0; j < 4; j++) {
            const float* x = S[j].x;
            int c = j * 16 + cb;
            float p0 = __expf(x[0] - mn0), p1 = __expf(x[1] - mn0);
            float p4 = __expf(x[4] - mn0), p5 = __expf(x[5] - mn0);
            float p2 = __expf(x[2] - mn1), p3 = __expf(x[3] - mn1);
            float p6 = __expf(x[6] - mn1), p7 = __expf(x[7] - mn1);
            s0 += p0 + p1 + p4 + p5;
            s1 += p2 + p3 + p6 + p7;
            *(__half2*)(prow0 + c)     = __floats2half2_rn(p0, p1);
            *(__half2*)(prow0 + c + 8) = __floats2half2_rn(p4, p5);
            *(__half2*)(prow1 + c)     = __floats2half2_rn(p2, p3);
            *(__half2*)(prow1 + c + 8) = __floats2half2_rn(p6, p7);
        }
        s0 += __shfl_xor_sync(0xffffffffu, s0, 1);
        s0 += __shfl_xor_sync(0xffffffffu, s0, 2);
        s1 += __shfl_xor_sync(0xffffffffu, s1, 1);
        s1 += __shfl_xor_sync(0xffffffffu, s1, 2);

        l0 = l0 * a0 + s0;  l1 = l1 * a1 + s1;
        m0 = mn0;           m1 = mn1;

        // rescale O accumulators by alpha (per fragment row)
        #pragma unroll
        for (int j = 0; j < 4; j++) {
            float* x = O[j].x;
            x[0] *= a0; x[1] *= a0; x[4] *= a0; x[5] *= a0;
            x[2] *= a1; x[3] *= a1; x[6] *= a1; x[7] *= a1;
        }
        __syncwarp();

        // ---- O += P V ----
        #pragma unroll
        for (int kk = 0; kk < 4; kk++) {
            wmma::fragment<wmma::matrix_a, 16, 16, 16, __half, wmma::row_major> af;
            wmma::load_matrix_sync(af, Ps + wrow * FLD + kk * 16, FLD);
            #pragma unroll
            for (int j = 0; j < 4; j++) {
                wmma::fragment<wmma::matrix_b, 16, 16, 16, __half, wmma::row_major> bf;
                wmma::load_matrix_sync(bf, Vs + st * KVS + (kk * 16) * FLD + j * 16, FLD);
                wmma::mma_sync(O[j], af, bf, O[j]);
            }
        }
        __syncthreads();
    }

    // ---- epilogue: normalize + write ctx [B,SQ,D] half ----
    float il0 = 1.0f / l0, il1 = 1.0f / l1;
    int row0 = q0 + wrow + (lane >> 2);
    __half* o0 = CTX + (size_t)(b * SQL + row0) * DMODEL + h * HDIM + cb;
    __half* o1 = o0 + 8 * DMODEL;
    #pragma unroll
    for (int j = 0; j < 4; j++) {
        const float* x = O[j].x;
        int c = j * 16;
        *(__half2*)(o0 + c)     = __floats2half2_rn(x[0] * il0, x[1] * il0);
        *(__half2*)(o0 + c + 8) = __floats2half2_rn(x[4] * il0, x[5] * il0);
        *(__half2*)(o1 + c)     = __floats2half2_rn(x[2] * il1, x[3] * il1);
        *(__half2*)(o1 + c + 8) = __floats2half2_rn(x[6] * il1, x[7] * il1);
    }
}

// ---------------- host ----------------
extern "C" void kernel_launch(void* const* d_in, const int* in_sizes, int n_in,
                              void* d_out, int out_size) {
    const float* x_q  = (const float*)d_in[0];
    const float* x_kv = (const float*)d_in[1];
    const float* wq   = (const float*)d_in[2];
    const float* bq   = (const float*)d_in[3];
    const float* wk   = (const float*)d_in[4];
    const float* bk   = (const float*)d_in[5];
    const float* wv   = (const float*)d_in[6];
    const float* bv   = (const float*)d_in[7];
    const float* wo   = (const float*)d_in[8];
    const float* bo   = (const float*)d_in[9];
    float* out = (float*)d_out;

    void *p_xq, *p_xkv, *p_wq, *p_wk, *p_wv, *p_wo;
    void *p_qh, *p_kh, *p_vh, *p_ctx;
    cudaGetSymbolAddress(&p_xq,  g_xq_h);
    cudaGetSymbolAddress(&p_xkv, g_xkv_h);
    cudaGetSymbolAddress(&p_wq,  g_wq_h);
    cudaGetSymbolAddress(&p_wk,  g_wk_h);
    cudaGetSymbolAddress(&p_wv,  g_wv_h);
    cudaGetSymbolAddress(&p_wo,  g_wo_h);
    cudaGetSymbolAddress(&p_qh,  g_qh);
    cudaGetSymbolAddress(&p_kh,  g_kh);
    cudaGetSymbolAddress(&p_vh,  g_vh);
    cudaGetSymbolAddress(&p_ctx, g_ctx_h);

    cudaFuncSetAttribute(flash2, cudaFuncAttributeMaxDynamicSharedMemorySize, FSMEM_BYTES);

    const int CT = 256;
    int nX = MQ * DMODEL / 4;
    int nW = DMODEL * DMODEL / 4;
    cvt_f32_f16<<<(nX + CT - 1) / CT, CT>>>(x_q,  (__half*)p_xq,  nX);
    cvt_f32_f16<<<(nX + CT - 1) / CT, CT>>>(x_kv, (__half*)p_xkv, nX);
    cvt_f32_f16<<<(nW + CT - 1) / CT, CT>>>(wq, (__half*)p_wq, nW);
    cvt_f32_f16<<<(nW + CT - 1) / CT, CT>>>(wk, (__half*)p_wk, nW);
    cvt_f32_f16<<<(nW + CT - 1) / CT, CT>>>(wv, (__half*)p_wv, nW);
    cvt_f32_f16<<<(nW + CT - 1) / CT, CT>>>(wo, (__half*)p_wo, nW);

    // fused projections (bias + rope + relayout in epilogue)
    dim3 ggrid(DMODEL / GBN, MQ / GBM);
    gemm_fused<1><<<ggrid, 256>>>((const __half*)p_xq,  (const __half*)p_wq, bq, p_qh, 0.125f);
    gemm_fused<1><<<ggrid, 256>>>((const __half*)p_xkv, (const __half*)p_wk, bk, p_kh, 1.0f);
    gemm_fused<2><<<ggrid, 256>>>((const __half*)p_xkv, (const __half*)p_wv, bv, p_vh, 1.0f);

    // flash attention
    dim3 fgrid(SQL / FQT, NH, BB);
    flash2<<<fgrid, 256, FSMEM_BYTES>>>((const __half*)p_qh, (const __half*)p_kh,
                                        (const __half*)p_vh, (__half*)p_ctx);

    // output projection (+bias fused)
    gemm_fused<0><<<ggrid, 256>>>((const __half*)p_ctx, (const __half*)p_wo, bo, out, 1.0f);
}

// round 9
// speedup vs baseline: 1.8306x; 1.0580x over previous
#include <cuda_runtime.h>
#include <cuda_fp16.h>
#include <mma.h>
#include <stdint.h>

using namespace nvcuda;

// Problem constants
#define BB     2
#define SQL    2048
#define SKVL   2048
#define DMODEL 1024
#define NH     16
#define HDIM   64
#define MQ     (BB*SQL)    // 4096
#define MKV    (BB*SKVL)   // 4096

// ---------------- scratch (device globals; no runtime allocation) ----------------
__device__ __half g_xq_h [MQ*DMODEL];
__device__ __half g_xkv_h[MKV*DMODEL];
__device__ __half g_wq_h [DMODEL*DMODEL];
__device__ __half g_wk_h [DMODEL*DMODEL];
__device__ __half g_wv_h [DMODEL*DMODEL];
__device__ __half g_wo_h [DMODEL*DMODEL];
__device__ __half g_qh   [MQ*DMODEL];   // [B,H,SQ,HD], pre-scaled by 1/8, rope applied
__device__ __half g_kh   [MKV*DMODEL];  // [B,H,SKV,HD], rope applied
__device__ __half g_vh   [MKV*DMODEL];  // [B,H,SKV,HD]
__device__ __half g_ctx_h[MQ*DMODEL];   // [B,SQ,D]

// ---------------- cp.async helpers ----------------
__device__ __forceinline__ void cp16(void* smem, const void* gmem) {
    uint32_t s = (uint32_t)__cvta_generic_to_shared(smem);
    asm volatile("cp.async.cg.shared.global [%0], [%1], 16;\n" :: "r"(s), "l"(gmem));
}
__device__ __forceinline__ void cp_commit() { asm volatile("cp.async.commit_group;\n"); }
template<int N> __device__ __forceinline__ void cp_wait() {
    asm volatile("cp.async.wait_group %0;\n" :: "n"(N));
}

// ---------------- fused fp32->fp16 convert (all 6 tensors, one launch) ----------------
__global__ void cvt_all(const float* __restrict__ xq, const float* __restrict__ xkv,
                        const float* __restrict__ wq, const float* __restrict__ wk,
                        const float* __restrict__ wv, const float* __restrict__ wo,
                        __half* oxq, __half* oxkv, __half* owq, __half* owk,
                        __half* owv, __half* owo) {
    int i = blockIdx.x * blockDim.x + threadIdx.x;   // float4 index, total 3M
    const float* src; __half* dst; int off;
    if (i < 1048576)      { src = xq;  dst = oxq;  off = i; }
    else if (i < 2097152) { src = xkv; dst = oxkv; off = i - 1048576; }
    else {
        int j = i - 2097152;
        int w = j >> 18;            // 0..3, 256K float4 each
        off = j & 262143;
        switch (w) {
            case 0: src = wq; dst = owq; break;
            case 1: src = wk; dst = owk; break;
            case 2: src = wv; dst = owv; break;
            default: src = wo; dst = owo; break;
        }
    }
    float4 v = reinterpret_cast<const float4*>(src)[off];
    reinterpret_cast<__half2*>(dst)[2*off]   = __floats2half2_rn(v.x, v.y);
    reinterpret_cast<__half2*>(dst)[2*off+1] = __floats2half2_rn(v.z, v.w);
}

// ---------------- WMMA GEMM mainloop (3-stage cp.async, 1 sync/iter) ----------------
// C[128,128] tile of A[M,1024] * W[1024,1024]^T.  256 threads, warp layout 4x2.
#define GBM 128
#define GBN 128
#define GBK 32
#define GLD 40
#define GST_HALFS (GBM * GLD)              // one matrix, one stage: 5120 halfs
#define GSTAGE_BYTES (2 * GST_HALFS * 2)   // A+B one stage: 20480 B
#define GEMM_SMEM (3 * GSTAGE_BYTES)       // 61440 B

// acc fragment layout (sm_80+ de-facto, m16n16k16 f32):
//   elem e: row = (lane>>2) + 8*((e>>1)&1), col = (lane&3)*2 + (e&1) + 8*(e>>2)

__device__ __forceinline__ void gemm_mainloop(
    const __half* __restrict__ A, const __half* __restrict__ Bm,
    char* dsm, int bm, int bn,
    wmma::fragment<wmma::accumulator, 16, 16, 16, float> (&acc)[2][4]) {

    const int K = DMODEL;
    int tid  = threadIdx.x;
    int warp = tid >> 5;
    int wm   = warp & 3;
    int wn   = warp >> 2;

    #pragma unroll
    for (int i = 0; i < 2; i++)
        #pragma unroll
        for (int j = 0; j < 4; j++)
            wmma::fill_fragment(acc[i][j], 0.0f);

    auto stA = [&](int st) { return (__half*)(dsm + st * GSTAGE_BYTES); };
    auto stB = [&](int st) { return (__half*)(dsm + st * GSTAGE_BYTES) + GST_HALFS; };

    int lrow = tid >> 2;          // 0..63
    int lcol = (tid & 3) * 8;     // 0,8,16,24

    auto load_stage = [&](int st, int kt) {
        int k0 = kt * GBK;
        __half* As = stA(st);
        __half* Bs = stB(st);
        #pragma unroll
        for (int p = 0; p < 2; p++) {
            int r = lrow + p * 64;
            cp16(As + r * GLD + lcol, A  + (size_t)(bm + r) * K + k0 + lcol);
            cp16(Bs + r * GLD + lcol, Bm + (size_t)(bn + r) * K + k0 + lcol);
        }
    };

    load_stage(0, 0); cp_commit();
    load_stage(1, 1); cp_commit();

    const int NK = K / GBK; // 32
    for (int kt = 0; kt < NK; kt++) {
        int st = kt % 3;
        if (kt == NK - 1) cp_wait<0>(); else cp_wait<1>();
        __syncthreads();
        if (kt + 2 < NK) { load_stage((kt + 2) % 3, kt + 2); cp_commit(); }

        __half* As = stA(st);
        __half* Bs = stB(st);
        #pragma unroll
        for (int kk = 0; kk < GBK; kk += 16) {
            wmma::fragment<wmma::matrix_a, 16, 16, 16, __half, wmma::row_major> af[2];
            wmma::fragment<wmma::matrix_b, 16, 16, 16, __half, wmma::col_major> bf[4];
            #pragma unroll
            for (int i = 0; i < 2; i++)
                wmma::load_matrix_sync(af[i], As + (wm * 32 + i * 16) * GLD + kk, GLD);
            #pragma unroll
            for (int j = 0; j < 4; j++)
                wmma::load_matrix_sync(bf[j], Bs + (wn * 64 + j * 16) * GLD + kk, GLD);
            #pragma unroll
            for (int i = 0; i < 2; i++)
                #pragma unroll
                for (int j = 0; j < 4; j++)
                    wmma::mma_sync(acc[i][j], af[i], bf[j], acc[i][j]);
        }
    }
}

// ---------------- combined Q/K/V projection kernel (grid.z selects) ----------------
// z=0: Q = x_q*wq^T + bq, rope, *0.125 -> g_qh
// z=1: K = x_kv*wk^T + bk, rope       -> g_kh
// z=2: V = x_kv*wv^T + bv             -> g_vh
__global__ __launch_bounds__(256, 2)
void gemm_proj(const __half* __restrict__ xq, const __half* __restrict__ xkv,
               const __half* __restrict__ wq, const __half* __restrict__ wk,
               const __half* __restrict__ wv,
               const float* __restrict__ bq, const float* __restrict__ bk,
               const float* __restrict__ bv,
               __half* __restrict__ qh, __half* __restrict__ kh, __half* __restrict__ vh) {
    extern __shared__ char dsm[];
    int z = blockIdx.z;
    const __half* A  = (z == 0) ? xq : xkv;
    const __half* Bm = (z == 0) ? wq : (z == 1) ? wk : wv;
    const float* bias = (z == 0) ? bq : (z == 1) ? bk : bv;
    __half* Oh = (z == 0) ? qh : (z == 1) ? kh : vh;
    float scale = (z == 0) ? 0.125f : 1.0f;
    bool do_rope = (z < 2);

    int bm = blockIdx.y * GBM;
    int bn = blockIdx.x * GBN;

    wmma::fragment<wmma::accumulator, 16, 16, 16, float> acc[2][4];
    gemm_mainloop(A, Bm, dsm, bm, bn, acc);

    int lane = threadIdx.x & 31;
    int warp = threadIdx.x >> 5;
    int wm = warp & 3, wn = warp >> 2;

    #pragma unroll
    for (int i = 0; i < 2; i++) {
        #pragma unroll
        for (int j = 0; j < 4; j++) {
            int r0 = bm + wm * 32 + i * 16 + (lane >> 2);
            int c0 = bn + wn * 64 + j * 16 + (lane & 3) * 2;
            const float* x = acc[i][j].x;
            #pragma unroll
            for (int p = 0; p < 4; p++) {
                int row = r0 + ((p & 1) ? 8 : 0);
                int col = c0 + ((p & 2) ? 8 : 0);
                float xe = x[p * 2]     + bias[col];
                float xo = x[p * 2 + 1] + bias[col + 1];
                int head = col >> 6;
                int hd   = col & 63;
                int s    = row & (SQL - 1);
                int bi   = row >> 11;
                float re, ro;
                if (do_rope) {
                    int pr = hd >> 1;
                    float freq = expf(-(float)pr * (9.210340371976184f / 32.0f));
                    float ang  = (float)s * freq;
                    float cs = cosf(ang), sn = sinf(ang);
                    re = (xe * cs - xo * sn) * scale;
                    ro = (xe * sn + xo * cs) * scale;
                } else {
                    re = xe; ro = xo;
                }
                *(__half2*)(Oh + ((size_t)(bi * NH + head) * SQL + s) * HDIM + hd) =
                    __floats2half2_rn(re, ro);
            }
        }
    }
}

// ---------------- output projection kernel (f32 out + bias) ----------------
__global__ __launch_bounds__(256, 2)
void gemm_out(const __half* __restrict__ A, const __half* __restrict__ Bm,
              const float* __restrict__ bias, float* __restrict__ C) {
    extern __shared__ char dsm[];
    int bm = blockIdx.y * GBM;
    int bn = blockIdx.x * GBN;

    wmma::fragment<wmma::accumulator, 16, 16, 16, float> acc[2][4];
    gemm_mainloop(A, Bm, dsm, bm, bn, acc);

    int lane = threadIdx.x & 31;
    int warp = threadIdx.x >> 5;
    int wm = warp & 3, wn = warp >> 2;
    const int N = DMODEL;

    #pragma unroll
    for (int i = 0; i < 2; i++) {
        #pragma unroll
        for (int j = 0; j < 4; j++) {
            int r0 = bm + wm * 32 + i * 16 + (lane >> 2);
            int c0 = bn + wn * 64 + j * 16 + (lane & 3) * 2;
            const float* x = acc[i][j].x;
            float2 v;
            v.x = x[0] + bias[c0];     v.y = x[1] + bias[c0 + 1];
            *(float2*)(C + (size_t)r0 * N + c0) = v;
            v.x = x[2] + bias[c0];     v.y = x[3] + bias[c0 + 1];
            *(float2*)(C + (size_t)(r0 + 8) * N + c0) = v;
            v.x = x[4] + bias[c0 + 8]; v.y = x[5] + bias[c0 + 9];
            *(float2*)(C + (size_t)r0 * N + c0 + 8) = v;
            v.x = x[6] + bias[c0 + 8]; v.y = x[7] + bias[c0 + 9];
            *(float2*)(C + (size_t)(r0 + 8) * N + c0 + 8) = v;
        }
    }
}

// ---------------- flash attention: 128-q tiles, 3-stage KV pipeline, 1 sync/iter ----------------
#define FQT  128
#define FKT  64
#define FLD  72
#define KVS  (FKT * FLD)   // one K or V stage, in halfs

#define FSMEM_BYTES ((FQT*FLD + 3*KVS + 3*KVS + FQT*FLD) * 2)   // 92160 B

__global__ __launch_bounds__(256)
void flash3(const __half* __restrict__ Q, const __half* __restrict__ K,
            const __half* __restrict__ V, __half* __restrict__ CTX) {
    extern __shared__ __half fsh[];
    __half* Qs = fsh;                 // FQT x FLD
    __half* Ks = Qs + FQT * FLD;      // 3 stages x FKT x FLD
    __half* Vs = Ks + 3 * KVS;        // 3 stages
    __half* Ps = Vs + 3 * KVS;        // FQT x FLD (per-warp private 16-row slices)

    int tid  = threadIdx.x;
    int lane = tid & 31;
    int warp = tid >> 5;
    int b    = blockIdx.z;
    int h    = blockIdx.y;
    int q0   = blockIdx.x * FQT;

    const __half* qptr  = Q + ((size_t)(b * NH + h) * SQL + q0) * HDIM;
    const __half* kbase = K + (size_t)(b * NH + h) * SKVL * HDIM;
    const __half* vbase = V + (size_t)(b * NH + h) * SKVL * HDIM;

    // load Q tile (128 x 64)
    for (int i = tid; i < FQT * 8; i += 256) {
        int r = i >> 3, c = (i & 7) * 8;
        *(float4*)(Qs + r * FLD + c) = *(const float4*)(qptr + r * HDIM + c);
    }

    auto copy_kv = [&](int st, int kt) {
        #pragma unroll
        for (int p = 0; p < 4; p++) {
            int i = tid + p * 256;
            int r = (i >> 3) & 63, c = (i & 7) * 8;
            if (i < 512)
                cp16(Ks + st * KVS + r * FLD + c, kbase + (size_t)(kt + r) * HDIM + c);
            else
                cp16(Vs + st * KVS + r * FLD + c, vbase + (size_t)(kt + r) * HDIM + c);
        }
    };

    copy_kv(0, 0); cp_commit();
    copy_kv(1, FKT); cp_commit();

    float m0 = -1e30f, m1 = -1e30f, l0 = 0.0f, l1 = 0.0f;

    wmma::fragment<wmma::accumulator, 16, 16, 16, float> O[4];
    #pragma unroll
    for (int j = 0; j < 4; j++) wmma::fill_fragment(O[j], 0.0f);

    int wrow = warp * 16;
    int cb   = (lane & 3) * 2;

    const int NT = SKVL / FKT;  // 32
    for (int t = 0; t < NT; t++) {
        int st = t % 3;
        if (t == NT - 1) cp_wait<0>(); else cp_wait<1>();
        __syncthreads();
        if (t + 2 < NT) { copy_kv((t + 2) % 3, (t + 2) * FKT); cp_commit(); }

        // ---- S = Q K^T (Q pre-scaled) ----
        wmma::fragment<wmma::accumulator, 16, 16, 16, float> S[4];
        #pragma unroll
        for (int j = 0; j < 4; j++) wmma::fill_fragment(S[j], 0.0f);
        #pragma unroll
        for (int kk = 0; kk < HDIM; kk += 16) {
            wmma::fragment<wmma::matrix_a, 16, 16, 16, __half, wmma::row_major> af;
            wmma::load_matrix_sync(af, Qs + wrow * FLD + kk, FLD);
            #pragma unroll
            for (int j = 0; j < 4; j++) {
                wmma::fragment<wmma::matrix_b, 16, 16, 16, __half, wmma::col_major> bf;
                wmma::load_matrix_sync(bf, Ks + st * KVS + (j * 16) * FLD + kk, FLD);
                wmma::mma_sync(S[j], af, bf, S[j]);
            }
        }

        // ---- online softmax in registers ----
        float mx0 = -1e30f, mx1 = -1e30f;
        #pragma unroll
        for (int j = 0; j < 4; j++) {
            const float* x = S[j].x;
            mx0 = fmaxf(mx0, fmaxf(fmaxf(x[0], x[1]), fmaxf(x[4], x[5])));
            mx1 = fmaxf(mx1, fmaxf(fmaxf(x[2], x[3]), fmaxf(x[6], x[7])));
        }
        mx0 = fmaxf(mx0, __shfl_xor_sync(0xffffffffu, mx0, 1));
        mx0 = fmaxf(mx0, __shfl_xor_sync(0xffffffffu, mx0, 2));
        mx1 = fmaxf(mx1, __shfl_xor_sync(0xffffffffu, mx1, 1));
        mx1 = fmaxf(mx1, __shfl_xor_sync(0xffffffffu, mx1, 2));

        float mn0 = fmaxf(m0, mx0), mn1 = fmaxf(m1, mx1);
        float a0  = __expf(m0 - mn0), a1 = __expf(m1 - mn1);

        __half* prow0 = Ps + (wrow + (lane >> 2)) * FLD;
        __half* prow1 = prow0 + 8 * FLD;
        float s0 = 0.0f, s1 = 0.0f;
        #pragma unroll
        for (int j = 0; j < 4; j++) {
            const float* x = S[j].x;
            int c = j * 16 + cb;
            float p0 = __expf(x[0] - mn0), p1 = __expf(x[1] - mn0);
            float p4 = __expf(x[4] - mn0), p5 = __expf(x[5] - mn0);
            float p2 = __expf(x[2] - mn1), p3 = __expf(x[3] - mn1);
            float p6 = __expf(x[6] - mn1), p7 = __expf(x[7] - mn1);
            s0 += p0 + p1 + p4 + p5;
            s1 += p2 + p3 + p6 + p7;
            *(__half2*)(prow0 + c)     = __floats2half2_rn(p0, p1);
            *(__half2*)(prow0 + c + 8) = __floats2half2_rn(p4, p5);
            *(__half2*)(prow1 + c)     = __floats2half2_rn(p2, p3);
            *(__half2*)(prow1 + c + 8) = __floats2half2_rn(p6, p7);
        }
        s0 += __shfl_xor_sync(0xffffffffu, s0, 1);
        s0 += __shfl_xor_sync(0xffffffffu, s0, 2);
        s1 += __shfl_xor_sync(0xffffffffu, s1, 1);
        s1 += __shfl_xor_sync(0xffffffffu, s1, 2);

        l0 = l0 * a0 + s0;  l1 = l1 * a1 + s1;
        m0 = mn0;           m1 = mn1;

        // rescale O accumulators by alpha (per fragment row)
        #pragma unroll
        for (int j = 0; j < 4; j++) {
            float* x = O[j].x;
            x[0] *= a0; x[1] *= a0; x[4] *= a0; x[5] *= a0;
            x[2] *= a1; x[3] *= a1; x[6] *= a1; x[7] *= a1;
        }
        __syncwarp();

        // ---- O += P V ----
        #pragma unroll
        for (int kk = 0; kk < 4; kk++) {
            wmma::fragment<wmma::matrix_a, 16, 16, 16, __half, wmma::row_major> af;
            wmma::load_matrix_sync(af, Ps + wrow * FLD + kk * 16, FLD);
            #pragma unroll
            for (int j = 0; j < 4; j++) {
                wmma::fragment<wmma::matrix_b, 16, 16, 16, __half, wmma::row_major> bf;
                wmma::load_matrix_sync(bf, Vs + st * KVS + (kk * 16) * FLD + j * 16, FLD);
                wmma::mma_sync(O[j], af, bf, O[j]);
            }
        }
    }

    // ---- epilogue: normalize + write ctx [B,SQ,D] half ----
    float il0 = 1.0f / l0, il1 = 1.0f / l1;
    int row0 = q0 + wrow + (lane >> 2);
    __half* o0 = CTX + (size_t)(b * SQL + row0) * DMODEL + h * HDIM + cb;
    __half* o1 = o0 + 8 * DMODEL;
    #pragma unroll
    for (int j = 0; j < 4; j++) {
        const float* x = O[j].x;
        int c = j * 16;
        *(__half2*)(o0 + c)     = __floats2half2_rn(x[0] * il0, x[1] * il0);
        *(__half2*)(o0 + c + 8) = __floats2half2_rn(x[4] * il0, x[5] * il0);
        *(__half2*)(o1 + c)     = __floats2half2_rn(x[2] * il1, x[3] * il1);
        *(__half2*)(o1 + c + 8) = __floats2half2_rn(x[6] * il1, x[7] * il1);
    }
}

// ---------------- host ----------------
extern "C" void kernel_launch(void* const* d_in, const int* in_sizes, int n_in,
                              void* d_out, int out_size) {
    const float* x_q  = (const float*)d_in[0];
    const float* x_kv = (const float*)d_in[1];
    const float* wq   = (const float*)d_in[2];
    const float* bq   = (const float*)d_in[3];
    const float* wk   = (const float*)d_in[4];
    const float* bk   = (const float*)d_in[5];
    const float* wv   = (const float*)d_in[6];
    const float* bv   = (const float*)d_in[7];
    const float* wo   = (const float*)d_in[8];
    const float* bo   = (const float*)d_in[9];
    float* out = (float*)d_out;

    void *p_xq, *p_xkv, *p_wq, *p_wk, *p_wv, *p_wo;
    void *p_qh, *p_kh, *p_vh, *p_ctx;
    cudaGetSymbolAddress(&p_xq,  g_xq_h);
    cudaGetSymbolAddress(&p_xkv, g_xkv_h);
    cudaGetSymbolAddress(&p_wq,  g_wq_h);
    cudaGetSymbolAddress(&p_wk,  g_wk_h);
    cudaGetSymbolAddress(&p_wv,  g_wv_h);
    cudaGetSymbolAddress(&p_wo,  g_wo_h);
    cudaGetSymbolAddress(&p_qh,  g_qh);
    cudaGetSymbolAddress(&p_kh,  g_kh);
    cudaGetSymbolAddress(&p_vh,  g_vh);
    cudaGetSymbolAddress(&p_ctx, g_ctx_h);

    cudaFuncSetAttribute(flash3,    cudaFuncAttributeMaxDynamicSharedMemorySize, FSMEM_BYTES);
    cudaFuncSetAttribute(gemm_proj, cudaFuncAttributeMaxDynamicSharedMemorySize, GEMM_SMEM);
    cudaFuncSetAttribute(gemm_out,  cudaFuncAttributeMaxDynamicSharedMemorySize, GEMM_SMEM);

    // one fused convert launch: 3M float4 chunks
    cvt_all<<<12288, 256>>>(x_q, x_kv, wq, wk, wv, wo,
                            (__half*)p_xq, (__half*)p_xkv, (__half*)p_wq,
                            (__half*)p_wk, (__half*)p_wv, (__half*)p_wo);

    // combined Q/K/V projections (bias + rope + relayout fused), one launch
    dim3 pgrid(DMODEL / GBN, MQ / GBM, 3);   // (8, 32, 3)
    gemm_proj<<<pgrid, 256, GEMM_SMEM>>>(
        (const __half*)p_xq, (const __half*)p_xkv,
        (const __half*)p_wq, (const __half*)p_wk, (const __half*)p_wv,
        bq, bk, bv,
        (__half*)p_qh, (__half*)p_kh, (__half*)p_vh);

    // flash attention
    dim3 fgrid(SQL / FQT, NH, BB);
    flash3<<<fgrid, 256, FSMEM_BYTES>>>((const __half*)p_qh, (const __half*)p_kh,
                                        (const __half*)p_vh, (__half*)p_ctx);

    // output projection (+bias fused)
    dim3 ogrid(DMODEL / GBN, MQ / GBM);
    gemm_out<<<ogrid, 256, GEMM_SMEM>>>((const __half*)p_ctx, (const __half*)p_wo, bo, out);
}

// round 10
// speedup vs baseline: 1.8692x; 1.0211x over previous
#include <cuda_runtime.h>
#include <cuda_fp16.h>
#include <mma.h>
#include <stdint.h>

using namespace nvcuda;

// Problem constants
#define BB     2
#define SQL    2048
#define SKVL   2048
#define DMODEL 1024
#define NH     16
#define HDIM   64
#define MQ     (BB*SQL)    // 4096
#define MKV    (BB*SKVL)   // 4096

// ---------------- scratch (device globals; no runtime allocation) ----------------
__device__ __half g_xq_h [MQ*DMODEL];
__device__ __half g_xkv_h[MKV*DMODEL];
__device__ __half g_wq_h [DMODEL*DMODEL];
__device__ __half g_wk_h [DMODEL*DMODEL];
__device__ __half g_wv_h [DMODEL*DMODEL];
__device__ __half g_wo_h [DMODEL*DMODEL];
__device__ __half g_qh   [MQ*DMODEL];   // [B,H,SQ,HD], pre-scaled by 1/8, rope applied
__device__ __half g_kh   [MKV*DMODEL];  // [B,H,SKV,HD], rope applied
__device__ __half g_vh   [MKV*DMODEL];  // [B,H,SKV,HD]
__device__ __half g_ctx_h[MQ*DMODEL];   // [B,SQ,D]

// ---------------- cp.async helpers ----------------
__device__ __forceinline__ void cp16(void* smem, const void* gmem) {
    uint32_t s = (uint32_t)__cvta_generic_to_shared(smem);
    asm volatile("cp.async.cg.shared.global [%0], [%1], 16;\n" :: "r"(s), "l"(gmem));
}
__device__ __forceinline__ void cp_commit() { asm volatile("cp.async.commit_group;\n"); }
template<int N> __device__ __forceinline__ void cp_wait() {
    asm volatile("cp.async.wait_group %0;\n" :: "n"(N));
}

// ---------------- fused fp32->fp16 convert (all 6 tensors, one launch) ----------------
__global__ void cvt_all(const float* __restrict__ xq, const float* __restrict__ xkv,
                        const float* __restrict__ wq, const float* __restrict__ wk,
                        const float* __restrict__ wv, const float* __restrict__ wo,
                        __half* oxq, __half* oxkv, __half* owq, __half* owk,
                        __half* owv, __half* owo) {
    int i = blockIdx.x * blockDim.x + threadIdx.x;   // float4 index, total 3M
    const float* src; __half* dst; int off;
    if (i < 1048576)      { src = xq;  dst = oxq;  off = i; }
    else if (i < 2097152) { src = xkv; dst = oxkv; off = i - 1048576; }
    else {
        int j = i - 2097152;
        int w = j >> 18;            // 0..3, 256K float4 each
        off = j & 262143;
        switch (w) {
            case 0: src = wq; dst = owq; break;
            case 1: src = wk; dst = owk; break;
            case 2: src = wv; dst = owv; break;
            default: src = wo; dst = owo; break;
        }
    }
    float4 v = reinterpret_cast<const float4*>(src)[off];
    reinterpret_cast<__half2*>(dst)[2*off]   = __floats2half2_rn(v.x, v.y);
    reinterpret_cast<__half2*>(dst)[2*off+1] = __floats2half2_rn(v.z, v.w);
}

// ---------------- WMMA GEMM mainloop (GBK=64, 3-stage cp.async, 1 sync/iter) ----------------
// C[128,128] tile of A[M,1024] * W[1024,1024]^T.  256 threads, warp layout 4x2.
#define GBM 128
#define GBN 128
#define GBK 64
#define GLD 72
#define GST_HALFS (GBM * GLD)              // one matrix, one stage: 9216 halfs
#define GSTAGE_BYTES (2 * GST_HALFS * 2)   // A+B one stage: 36864 B
#define GEMM_SMEM (3 * GSTAGE_BYTES)       // 110592 B

// acc fragment layout (sm_80+ de-facto, m16n16k16 f32):
//   elem e: row = (lane>>2) + 8*((e>>1)&1), col = (lane&3)*2 + (e&1) + 8*(e>>2)

__device__ __forceinline__ void gemm_mainloop(
    const __half* __restrict__ A, const __half* __restrict__ Bm,
    char* dsm, int bm, int bn,
    wmma::fragment<wmma::accumulator, 16, 16, 16, float> (&acc)[2][4]) {

    const int K = DMODEL;
    int tid  = threadIdx.x;
    int warp = tid >> 5;
    int wm   = warp & 3;
    int wn   = warp >> 2;

    #pragma unroll
    for (int i = 0; i < 2; i++)
        #pragma unroll
        for (int j = 0; j < 4; j++)
            wmma::fill_fragment(acc[i][j], 0.0f);

    auto stA = [&](int st) { return (__half*)(dsm + st * GSTAGE_BYTES); };
    auto stB = [&](int st) { return (__half*)(dsm + st * GSTAGE_BYTES) + GST_HALFS; };

    int lrow = tid >> 3;          // 0..31 base rows (each thread does 4 rows strided)
    int lcol = (tid & 7) * 8;     // 0..56

    auto load_stage = [&](int st, int kt) {
        int k0 = kt * GBK;
        __half* As = stA(st);
        __half* Bs = stB(st);
        #pragma unroll
        for (int p = 0; p < 4; p++) {
            int r = lrow + p * 32;
            cp16(As + r * GLD + lcol, A  + (size_t)(bm + r) * K + k0 + lcol);
            cp16(Bs + r * GLD + lcol, Bm + (size_t)(bn + r) * K + k0 + lcol);
        }
    };

    load_stage(0, 0); cp_commit();
    load_stage(1, 1); cp_commit();

    const int NK = K / GBK; // 16
    for (int kt = 0; kt < NK; kt++) {
        int st = kt % 3;
        if (kt == NK - 1) cp_wait<0>(); else cp_wait<1>();
        __syncthreads();
        if (kt + 2 < NK) { load_stage((kt + 2) % 3, kt + 2); cp_commit(); }

        __half* As = stA(st);
        __half* Bs = stB(st);
        #pragma unroll
        for (int kk = 0; kk < GBK; kk += 16) {
            wmma::fragment<wmma::matrix_a, 16, 16, 16, __half, wmma::row_major> af[2];
            wmma::fragment<wmma::matrix_b, 16, 16, 16, __half, wmma::col_major> bf[4];
            #pragma unroll
            for (int i = 0; i < 2; i++)
                wmma::load_matrix_sync(af[i], As + (wm * 32 + i * 16) * GLD + kk, GLD);
            #pragma unroll
            for (int j = 0; j < 4; j++)
                wmma::load_matrix_sync(bf[j], Bs + (wn * 64 + j * 16) * GLD + kk, GLD);
            #pragma unroll
            for (int i = 0; i < 2; i++)
                #pragma unroll
                for (int j = 0; j < 4; j++)
                    wmma::mma_sync(acc[i][j], af[i], bf[j], acc[i][j]);
        }
    }
}

// ---------------- combined Q/K/V projection kernel (grid.z selects) ----------------
// z=0: Q = x_q*wq^T + bq, rope, *0.125 -> g_qh
// z=1: K = x_kv*wk^T + bk, rope       -> g_kh
// z=2: V = x_kv*wv^T + bv             -> g_vh
__global__ __launch_bounds__(256, 2)
void gemm_proj(const __half* __restrict__ xq, const __half* __restrict__ xkv,
               const __half* __restrict__ wq, const __half* __restrict__ wk,
               const __half* __restrict__ wv,
               const float* __restrict__ bq, const float* __restrict__ bk,
               const float* __restrict__ bv,
               __half* __restrict__ qh, __half* __restrict__ kh, __half* __restrict__ vh) {
    extern __shared__ char dsm[];
    int z = blockIdx.z;
    const __half* A  = (z == 0) ? xq : xkv;
    const __half* Bm = (z == 0) ? wq : (z == 1) ? wk : wv;
    const float* bias = (z == 0) ? bq : (z == 1) ? bk : bv;
    __half* Oh = (z == 0) ? qh : (z == 1) ? kh : vh;
    float scale = (z == 0) ? 0.125f : 1.0f;
    bool do_rope = (z < 2);

    int bm = blockIdx.y * GBM;
    int bn = blockIdx.x * GBN;

    wmma::fragment<wmma::accumulator, 16, 16, 16, float> acc[2][4];
    gemm_mainloop(A, Bm, dsm, bm, bn, acc);

    int lane = threadIdx.x & 31;
    int warp = threadIdx.x >> 5;
    int wm = warp & 3, wn = warp >> 2;

    #pragma unroll
    for (int i = 0; i < 2; i++) {
        #pragma unroll
        for (int j = 0; j < 4; j++) {
            int r0 = bm + wm * 32 + i * 16 + (lane >> 2);
            int c0 = bn + wn * 64 + j * 16 + (lane & 3) * 2;
            const float* x = acc[i][j].x;
            #pragma unroll
            for (int p = 0; p < 4; p++) {
                int row = r0 + ((p & 1) ? 8 : 0);
                int col = c0 + ((p & 2) ? 8 : 0);
                float xe = x[p * 2]     + bias[col];
                float xo = x[p * 2 + 1] + bias[col + 1];
                int head = col >> 6;
                int hd   = col & 63;
                int s    = row & (SQL - 1);
                int bi   = row >> 11;
                float re, ro;
                if (do_rope) {
                    int pr = hd >> 1;
                    float freq = expf(-(float)pr * (9.210340371976184f / 32.0f));
                    float ang  = (float)s * freq;
                    float cs = cosf(ang), sn = sinf(ang);
                    re = (xe * cs - xo * sn) * scale;
                    ro = (xe * sn + xo * cs) * scale;
                } else {
                    re = xe; ro = xo;
                }
                *(__half2*)(Oh + ((size_t)(bi * NH + head) * SQL + s) * HDIM + hd) =
                    __floats2half2_rn(re, ro);
            }
        }
    }
}

// ---------------- output projection kernel (f32 out + bias) ----------------
__global__ __launch_bounds__(256, 2)
void gemm_out(const __half* __restrict__ A, const __half* __restrict__ Bm,
              const float* __restrict__ bias, float* __restrict__ C) {
    extern __shared__ char dsm[];
    int bm = blockIdx.y * GBM;
    int bn = blockIdx.x * GBN;

    wmma::fragment<wmma::accumulator, 16, 16, 16, float> acc[2][4];
    gemm_mainloop(A, Bm, dsm, bm, bn, acc);

    int lane = threadIdx.x & 31;
    int warp = threadIdx.x >> 5;
    int wm = warp & 3, wn = warp >> 2;
    const int N = DMODEL;

    #pragma unroll
    for (int i = 0; i < 2; i++) {
        #pragma unroll
        for (int j = 0; j < 4; j++) {
            int r0 = bm + wm * 32 + i * 16 + (lane >> 2);
            int c0 = bn + wn * 64 + j * 16 + (lane & 3) * 2;
            const float* x = acc[i][j].x;
            float2 v;
            v.x = x[0] + bias[c0];     v.y = x[1] + bias[c0 + 1];
            *(float2*)(C + (size_t)r0 * N + c0) = v;
            v.x = x[2] + bias[c0];     v.y = x[3] + bias[c0 + 1];
            *(float2*)(C + (size_t)(r0 + 8) * N + c0) = v;
            v.x = x[4] + bias[c0 + 8]; v.y = x[5] + bias[c0 + 9];
            *(float2*)(C + (size_t)r0 * N + c0 + 8) = v;
            v.x = x[6] + bias[c0 + 8]; v.y = x[7] + bias[c0 + 9];
            *(float2*)(C + (size_t)(r0 + 8) * N + c0 + 8) = v;
        }
    }
}

// ---------------- flash attention: 128-q tiles, 3-stage KV pipeline, 1 sync/iter ----------------
#define FQT  128
#define FKT  64
#define FLD  72
#define KVS  (FKT * FLD)   // one K or V stage, in halfs

#define FSMEM_BYTES ((FQT*FLD + 3*KVS + 3*KVS + FQT*FLD) * 2)   // 92160 B

__global__ __launch_bounds__(256)
void flash3(const __half* __restrict__ Q, const __half* __restrict__ K,
            const __half* __restrict__ V, __half* __restrict__ CTX) {
    extern __shared__ __half fsh[];
    __half* Qs = fsh;                 // FQT x FLD
    __half* Ks = Qs + FQT * FLD;      // 3 stages x FKT x FLD
    __half* Vs = Ks + 3 * KVS;        // 3 stages
    __half* Ps = Vs + 3 * KVS;        // FQT x FLD (per-warp private 16-row slices)

    int tid  = threadIdx.x;
    int lane = tid & 31;
    int warp = tid >> 5;
    int b    = blockIdx.z;
    int h    = blockIdx.y;
    int q0   = blockIdx.x * FQT;

    const __half* qptr  = Q + ((size_t)(b * NH + h) * SQL + q0) * HDIM;
    const __half* kbase = K + (size_t)(b * NH + h) * SKVL * HDIM;
    const __half* vbase = V + (size_t)(b * NH + h) * SKVL * HDIM;

    // load Q tile (128 x 64)
    for (int i = tid; i < FQT * 8; i += 256) {
        int r = i >> 3, c = (i & 7) * 8;
        *(float4*)(Qs + r * FLD + c) = *(const float4*)(qptr + r * HDIM + c);
    }

    auto copy_kv = [&](int st, int kt) {
        #pragma unroll
        for (int p = 0; p < 4; p++) {
            int i = tid + p * 256;
            int r = (i >> 3) & 63, c = (i & 7) * 8;
            if (i < 512)
                cp16(Ks + st * KVS + r * FLD + c, kbase + (size_t)(kt + r) * HDIM + c);
            else
                cp16(Vs + st * KVS + r * FLD + c, vbase + (size_t)(kt + r) * HDIM + c);
        }
    };

    copy_kv(0, 0); cp_commit();
    copy_kv(1, FKT); cp_commit();

    float m0 = -1e30f, m1 = -1e30f, l0 = 0.0f, l1 = 0.0f;

    wmma::fragment<wmma::accumulator, 16, 16, 16, float> O[4];
    #pragma unroll
    for (int j = 0; j < 4; j++) wmma::fill_fragment(O[j], 0.0f);

    int wrow = warp * 16;
    int cb   = (lane & 3) * 2;

    const int NT = SKVL / FKT;  // 32
    for (int t = 0; t < NT; t++) {
        int st = t % 3;
        if (t == NT - 1) cp_wait<0>(); else cp_wait<1>();
        __syncthreads();
        if (t + 2 < NT) { copy_kv((t + 2) % 3, (t + 2) * FKT); cp_commit(); }

        // ---- S = Q K^T (Q pre-scaled) ----
        wmma::fragment<wmma::accumulator, 16, 16, 16, float> S[4];
        #pragma unroll
        for (int j = 0; j < 4; j++) wmma::fill_fragment(S[j], 0.0f);
        #pragma unroll
        for (int kk = 0; kk < HDIM; kk += 16) {
            wmma::fragment<wmma::matrix_a, 16, 16, 16, __half, wmma::row_major> af;
            wmma::load_matrix_sync(af, Qs + wrow * FLD + kk, FLD);
            #pragma unroll
            for (int j = 0; j < 4; j++) {
                wmma::fragment<wmma::matrix_b, 16, 16, 16, __half, wmma::col_major> bf;
                wmma::load_matrix_sync(bf, Ks + st * KVS + (j * 16) * FLD + kk, FLD);
                wmma::mma_sync(S[j], af, bf, S[j]);
            }
        }

        // ---- online softmax in registers ----
        float mx0 = -1e30f, mx1 = -1e30f;
        #pragma unroll
        for (int j = 0; j < 4; j++) {
            const float* x = S[j].x;
            mx0 = fmaxf(mx0, fmaxf(fmaxf(x[0], x[1]), fmaxf(x[4], x[5])));
            mx1 = fmaxf(mx1, fmaxf(fmaxf(x[2], x[3]), fmaxf(x[6], x[7])));
        }
        mx0 = fmaxf(mx0, __shfl_xor_sync(0xffffffffu, mx0, 1));
        mx0 = fmaxf(mx0, __shfl_xor_sync(0xffffffffu, mx0, 2));
        mx1 = fmaxf(mx1, __shfl_xor_sync(0xffffffffu, mx1, 1));
        mx1 = fmaxf(mx1, __shfl_xor_sync(0xffffffffu, mx1, 2));

        float mn0 = fmaxf(m0, mx0), mn1 = fmaxf(m1, mx1);
        float a0  = __expf(m0 - mn0), a1 = __expf(m1 - mn1);

        __half* prow0 = Ps + (wrow + (lane >> 2)) * FLD;
        __half* prow1 = prow0 + 8 * FLD;
        float s0 = 0.0f, s1 = 0.0f;
        #pragma unroll
        for (int j = 0; j < 4; j++) {
            const float* x = S[j].x;
            int c = j * 16 + cb;
            float p0 = __expf(x[0] - mn0), p1 = __expf(x[1] - mn0);
            float p4 = __expf(x[4] - mn0), p5 = __expf(x[5] - mn0);
            float p2 = __expf(x[2] - mn1), p3 = __expf(x[3] - mn1);
            float p6 = __expf(x[6] - mn1), p7 = __expf(x[7] - mn1);
            s0 += p0 + p1 + p4 + p5;
            s1 += p2 + p3 + p6 + p7;
            *(__half2*)(prow0 + c)     = __floats2half2_rn(p0, p1);
            *(__half2*)(prow0 + c + 8) = __floats2half2_rn(p4, p5);
            *(__half2*)(prow1 + c)     = __floats2half2_rn(p2, p3);
            *(__half2*)(prow1 + c + 8) = __floats2half2_rn(p6, p7);
        }
        s0 += __shfl_xor_sync(0xffffffffu, s0, 1);
        s0 += __shfl_xor_sync(0xffffffffu, s0, 2);
        s1 += __shfl_xor_sync(0xffffffffu, s1, 1);
        s1 += __shfl_xor_sync(0xffffffffu, s1, 2);

        l0 = l0 * a0 + s0;  l1 = l1 * a1 + s1;
        m0 = mn0;           m1 = mn1;

        // rescale O accumulators by alpha (per fragment row)
        #pragma unroll
        for (int j = 0; j < 4; j++) {
            float* x = O[j].x;
            x[0] *= a0; x[1] *= a0; x[4] *= a0; x[5] *= a0;
            x[2] *= a1; x[3] *= a1; x[6] *= a1; x[7] *= a1;
        }
        __syncwarp();

        // ---- O += P V ----
        #pragma unroll
        for (int kk = 0; kk < 4; kk++) {
            wmma::fragment<wmma::matrix_a, 16, 16, 16, __half, wmma::row_major> af;
            wmma::load_matrix_sync(af, Ps + wrow * FLD + kk * 16, FLD);
            #pragma unroll
            for (int j = 0; j < 4; j++) {
                wmma::fragment<wmma::matrix_b, 16, 16, 16, __half, wmma::row_major> bf;
                wmma::load_matrix_sync(bf, Vs + st * KVS + (kk * 16) * FLD + j * 16, FLD);
                wmma::mma_sync(O[j], af, bf, O[j]);
            }
        }
    }

    // ---- epilogue: normalize + write ctx [B,SQ,D] half ----
    float il0 = 1.0f / l0, il1 = 1.0f / l1;
    int row0 = q0 + wrow + (lane >> 2);
    __half* o0 = CTX + (size_t)(b * SQL + row0) * DMODEL + h * HDIM + cb;
    __half* o1 = o0 + 8 * DMODEL;
    #pragma unroll
    for (int j = 0; j < 4; j++) {
        const float* x = O[j].x;
        int c = j * 16;
        *(__half2*)(o0 + c)     = __floats2half2_rn(x[0] * il0, x[1] * il0);
        *(__half2*)(o0 + c + 8) = __floats2half2_rn(x[4] * il0, x[5] * il0);
        *(__half2*)(o1 + c)     = __floats2half2_rn(x[2] * il1, x[3] * il1);
        *(__half2*)(o1 + c + 8) = __floats2half2_rn(x[6] * il1, x[7] * il1);
    }
}

// ---------------- host ----------------
extern "C" void kernel_launch(void* const* d_in, const int* in_sizes, int n_in,
                              void* d_out, int out_size) {
    const float* x_q  = (const float*)d_in[0];
    const float* x_kv = (const float*)d_in[1];
    const float* wq   = (const float*)d_in[2];
    const float* bq   = (const float*)d_in[3];
    const float* wk   = (const float*)d_in[4];
    const float* bk   = (const float*)d_in[5];
    const float* wv   = (const float*)d_in[6];
    const float* bv   = (const float*)d_in[7];
    const float* wo   = (const float*)d_in[8];
    const float* bo   = (const float*)d_in[9];
    float* out = (float*)d_out;

    void *p_xq, *p_xkv, *p_wq, *p_wk, *p_wv, *p_wo;
    void *p_qh, *p_kh, *p_vh, *p_ctx;
    cudaGetSymbolAddress(&p_xq,  g_xq_h);
    cudaGetSymbolAddress(&p_xkv, g_xkv_h);
    cudaGetSymbolAddress(&p_wq,  g_wq_h);
    cudaGetSymbolAddress(&p_wk,  g_wk_h);
    cudaGetSymbolAddress(&p_wv,  g_wv_h);
    cudaGetSymbolAddress(&p_wo,  g_wo_h);
    cudaGetSymbolAddress(&p_qh,  g_qh);
    cudaGetSymbolAddress(&p_kh,  g_kh);
    cudaGetSymbolAddress(&p_vh,  g_vh);
    cudaGetSymbolAddress(&p_ctx, g_ctx_h);

    cudaFuncSetAttribute(flash3,    cudaFuncAttributeMaxDynamicSharedMemorySize, FSMEM_BYTES);
    cudaFuncSetAttribute(gemm_proj, cudaFuncAttributeMaxDynamicSharedMemorySize, GEMM_SMEM);
    cudaFuncSetAttribute(gemm_out,  cudaFuncAttributeMaxDynamicSharedMemorySize, GEMM_SMEM);

    // one fused convert launch: 3M float4 chunks
    cvt_all<<<12288, 256>>>(x_q, x_kv, wq, wk, wv, wo,
                            (__half*)p_xq, (__half*)p_xkv, (__half*)p_wq,
                            (__half*)p_wk, (__half*)p_wv, (__half*)p_wo);

    // combined Q/K/V projections (bias + rope + relayout fused), one launch
    dim3 pgrid(DMODEL / GBN, MQ / GBM, 3);   // (8, 32, 3)
    gemm_proj<<<pgrid, 256, GEMM_SMEM>>>(
        (const __half*)p_xq, (const __half*)p_xkv,
        (const __half*)p_wq, (const __half*)p_wk, (const __half*)p_wv,
        bq, bk, bv,
        (__half*)p_qh, (__half*)p_kh, (__half*)p_vh);

    // flash attention
    dim3 fgrid(SQL / FQT, NH, BB);
    flash3<<<fgrid, 256, FSMEM_BYTES>>>((const __half*)p_qh, (const __half*)p_kh,
                                        (const __half*)p_vh, (__half*)p_ctx);

    // output projection (+bias fused)
    dim3 ogrid(DMODEL / GBN, MQ / GBM);
    gemm_out<<<ogrid, 256, GEMM_SMEM>>>((const __half*)p_ctx, (const __half*)p_wo, bo, out);
}